// round 14
// baseline (speedup 1.0000x reference)
#include <cuda_runtime.h>
#include <cuda_bf16.h>
#include <math.h>

// ---------------------------------------------------------------------------
// Problem constants
// ---------------------------------------------------------------------------
#define BB    4
#define TT    8
#define RES   32
#define CC    128
#define LL    (TT * RES * RES)        // 8192
#define NTOK  (BB * LL)               // 32768
#define HID   (4 * CC)                // 512
#define TSP   4
#define WIN   512
#define NWIN  64
#define NH    4
#define HD    16
#define HCH   64

#define QSCALE 0.36067376022224085f   // 0.25 * log2(e)

// ---------------------------------------------------------------------------
// Scratch
// ---------------------------------------------------------------------------
__device__ __nv_bfloat16 g_img[(size_t)NTOK * CC];
__device__ __nv_bfloat16 g_att[(size_t)NTOK * CC];
__device__ float         g_xa [(size_t)NTOK * CC];
__device__ __nv_bfloat16 g_y1 [(size_t)NTOK * CC];
__device__ __nv_bfloat16 g_h  [(size_t)NTOK * HID];
__device__ __nv_bfloat16 g_qkvw[(size_t)3 * CC * CC];
__device__ __nv_bfloat16 g_projw[(size_t)CC * CC];
__device__ __nv_bfloat16 g_fc1w[(size_t)HID * CC];
__device__ __nv_bfloat16 g_fc2w[(size_t)CC * HID];
// window-major attention operands: [branch][win][head][j][d] (q scaled)
__device__ __nv_bfloat16 g_qw[(size_t)2 * NWIN * NH * WIN * HD];
__device__ __nv_bfloat16 g_kw[(size_t)2 * NWIN * NH * WIN * HD];
// transposed V: [branch][win][head][d][j]
__device__ __nv_bfloat16 g_vt[(size_t)2 * NWIN * NH * HD * WIN];

// ---------------------------------------------------------------------------
// fp32 -> bf16 weight conversion
// ---------------------------------------------------------------------------
__global__ void cvt4_kernel(const float* __restrict__ s0, __nv_bfloat16* __restrict__ d0, int n0,
                            const float* __restrict__ s1, __nv_bfloat16* __restrict__ d1, int n1,
                            const float* __restrict__ s2, __nv_bfloat16* __restrict__ d2, int n2,
                            const float* __restrict__ s3, __nv_bfloat16* __restrict__ d3, int n3) {
    int i = blockIdx.x * blockDim.x + threadIdx.x;
    if (i < n0) d0[i] = __float2bfloat16(s0[i]);
    if (i < n1) d1[i] = __float2bfloat16(s1[i]);
    if (i < n2) d2[i] = __float2bfloat16(s2[i]);
    if (i < n3) d3[i] = __float2bfloat16(s3[i]);
}

// ---------------------------------------------------------------------------
// LayerNorm: one warp per token; writes bf16
// ---------------------------------------------------------------------------
__global__ void ln_kernel(const float* __restrict__ x, const float* __restrict__ w,
                          const float* __restrict__ b, __nv_bfloat16* __restrict__ out) {
    int gw   = (blockIdx.x * blockDim.x + threadIdx.x) >> 5;
    int lane = threadIdx.x & 31;
    if (gw >= NTOK) return;
    float4 v = ((const float4*)(x + (size_t)gw * CC))[lane];
    float s = v.x + v.y + v.z + v.w;
    #pragma unroll
    for (int o = 16; o; o >>= 1) s += __shfl_xor_sync(0xffffffffu, s, o);
    float mu = s * (1.0f / CC);
    float dx = v.x - mu, dy = v.y - mu, dz = v.z - mu, dw = v.w - mu;
    float s2 = dx * dx + dy * dy + dz * dz + dw * dw;
    #pragma unroll
    for (int o = 16; o; o >>= 1) s2 += __shfl_xor_sync(0xffffffffu, s2, o);
    float rstd = rsqrtf(s2 * (1.0f / CC) + 1e-5f);
    float4 w4 = ((const float4*)w)[lane];
    float4 b4 = ((const float4*)b)[lane];
    float ox = dx * rstd * w4.x + b4.x;
    float oy = dy * rstd * w4.y + b4.y;
    float oz = dz * rstd * w4.z + b4.z;
    float ow = dw * rstd * w4.w + b4.w;
    __nv_bfloat162* op = (__nv_bfloat162*)(out + (size_t)gw * CC);
    op[lane * 2]     = __floats2bfloat162_rn(ox, oy);
    op[lane * 2 + 1] = __floats2bfloat162_rn(oz, ow);
}

// ---------------------------------------------------------------------------
// bf16 MMA GEMM, double-buffered via cp.async.
// MODE: 0 = plain/residual, 1 = +gelu, 2 = qkv window-scatter
// ---------------------------------------------------------------------------
#define GBM 128
#define GBN 64
#define GBK 32
#define APIT 40

#define CPA16(dst, src) \
    asm volatile("cp.async.cg.shared.global [%0], [%1], 16;" :: "r"(dst), "l"(src))

template<int MODE>
__global__ void gemm_mma(const __nv_bfloat16* __restrict__ A, const __nv_bfloat16* __restrict__ W,
                         const float* __restrict__ bias, const float* __restrict__ res,
                         float* __restrict__ outF, __nv_bfloat16* __restrict__ outH,
                         int N, int K, int M) {
    __shared__ __nv_bfloat16 sA[2][GBM][APIT];
    __shared__ __nv_bfloat16 sW[2][GBN][APIT];
    int tid = threadIdx.x;
    int wid = tid >> 5, lane = tid & 31;
    int warp_m = wid >> 1, warp_n = wid & 1;
    int tok0 = blockIdx.x * GBM;
    int f0   = blockIdx.y * GBN;

    float acc[2][4][4];
    #pragma unroll
    for (int i = 0; i < 2; i++)
        #pragma unroll
        for (int j = 0; j < 4; j++)
            #pragma unroll
            for (int r = 0; r < 4; r++) acc[i][j][r] = 0.0f;

    int rowT = tid >> 2, segT = (tid & 3) * 8;

    // prologue: stage k0=0 into buf 0
    {
        #pragma unroll
        for (int p = 0; p < 2; p++) {
            int row = rowT + p * 64;
            unsigned dst = (unsigned)__cvta_generic_to_shared(&sA[0][row][segT]);
            const __nv_bfloat16* src = A + (size_t)(tok0 + row) * K + segT;
            CPA16(dst, src);
        }
        unsigned dst = (unsigned)__cvta_generic_to_shared(&sW[0][rowT][segT]);
        const __nv_bfloat16* src = W + (size_t)(f0 + rowT) * K + segT;
        CPA16(dst, src);
        asm volatile("cp.async.commit_group;");
    }
    asm volatile("cp.async.wait_group 0;");
    __syncthreads();

    int nk = K / GBK;
    for (int it = 0; it < nk; it++) {
        int buf = it & 1;
        if (it + 1 < nk) {
            int k0 = (it + 1) * GBK;
            #pragma unroll
            for (int p = 0; p < 2; p++) {
                int row = rowT + p * 64;
                unsigned dst = (unsigned)__cvta_generic_to_shared(&sA[buf ^ 1][row][segT]);
                const __nv_bfloat16* src = A + (size_t)(tok0 + row) * K + k0 + segT;
                CPA16(dst, src);
            }
            unsigned dst = (unsigned)__cvta_generic_to_shared(&sW[buf ^ 1][rowT][segT]);
            const __nv_bfloat16* src = W + (size_t)(f0 + rowT) * K + k0 + segT;
            CPA16(dst, src);
            asm volatile("cp.async.commit_group;");
        }
        #pragma unroll
        for (int kk = 0; kk < GBK; kk += 16) {
            unsigned afrag[2][4], bfrag[4][2];
            int rr = (lane >> 2);
            int cc2 = kk + (lane & 3) * 2;
            #pragma unroll
            for (int i = 0; i < 2; i++) {
                int r = warp_m * 32 + i * 16 + rr;
                afrag[i][0] = *(const unsigned*)(&sA[buf][r][cc2]);
                afrag[i][1] = *(const unsigned*)(&sA[buf][r + 8][cc2]);
                afrag[i][2] = *(const unsigned*)(&sA[buf][r][cc2 + 8]);
                afrag[i][3] = *(const unsigned*)(&sA[buf][r + 8][cc2 + 8]);
            }
            #pragma unroll
            for (int j = 0; j < 4; j++) {
                int n = warp_n * 32 + j * 8 + rr;
                bfrag[j][0] = *(const unsigned*)(&sW[buf][n][cc2]);
                bfrag[j][1] = *(const unsigned*)(&sW[buf][n][cc2 + 8]);
            }
            #pragma unroll
            for (int i = 0; i < 2; i++)
                #pragma unroll
                for (int j = 0; j < 4; j++)
                    asm volatile(
                        "mma.sync.aligned.m16n8k16.row.col.f32.bf16.bf16.f32 "
                        "{%0,%1,%2,%3}, {%4,%5,%6,%7}, {%8,%9}, {%0,%1,%2,%3};"
                        : "+f"(acc[i][j][0]), "+f"(acc[i][j][1]),
                          "+f"(acc[i][j][2]), "+f"(acc[i][j][3])
                        : "r"(afrag[i][0]), "r"(afrag[i][1]),
                          "r"(afrag[i][2]), "r"(afrag[i][3]),
                          "r"(bfrag[j][0]), "r"(bfrag[j][1]));
        }
        if (it + 1 < nk) asm volatile("cp.async.wait_group 0;");
        __syncthreads();
    }

    if (MODE == 2) {
        // decode 4 distinct rows (token -> both-branch window coords)
        int bw0[2][2], bw1[2][2], j0[2][2], j1[2][2];
        #pragma unroll
        for (int i = 0; i < 2; i++)
            #pragma unroll
            for (int h = 0; h < 2; h++) {
                int n = tok0 + warp_m * 32 + i * 16 + (lane >> 2) + h * 8;
                int bq = n >> 13, l = n & 8191;
                int tc = l >> 10, hh = (l >> 5) & 31, ww = l & 31;
                int bq2 = bq * 2 + (tc >> 2), ts = tc & 3;
                bw0[i][h] = bq2 * 8 + (ww >> 2);
                j0[i][h]  = ts * 128 + hh * 4 + (ww & 3);
                bw1[i][h] = bq2 * 8 + (hh >> 2);
                j1[i][h]  = ts * 128 + (hh & 3) * 32 + ww;
            }
        #pragma unroll
        for (int j = 0; j < 4; j++) {
            int m = f0 + warp_n * 32 + j * 8 + (lane & 3) * 2;
            int part = m >> 7, mm = m & 127;
            int br = (mm >> 6) & 1, head = (mm >> 4) & 3, d = mm & 15;
            int hb = (br * NWIN * NH) + head;
            #pragma unroll
            for (int i = 0; i < 2; i++)
                #pragma unroll
                for (int h = 0; h < 2; h++) {
                    int bw = br ? bw1[i][h] : bw0[i][h];
                    int jj = br ? j1[i][h] : j0[i][h];
                    size_t base = ((size_t)(hb + bw * NH)) << 13;
                    float v0 = acc[i][j][h * 2 + 0];
                    float v1 = acc[i][j][h * 2 + 1];
                    if (part == 0) {
                        *(__nv_bfloat162*)(g_qw + base + jj * HD + d) =
                            __floats2bfloat162_rn(v0 * QSCALE, v1 * QSCALE);
                    } else if (part == 1) {
                        *(__nv_bfloat162*)(g_kw + base + jj * HD + d) =
                            __floats2bfloat162_rn(v0, v1);
                    } else {
                        g_vt[base + (size_t)d * WIN + jj]       = __float2bfloat16(v0);
                        g_vt[base + (size_t)(d + 1) * WIN + jj] = __float2bfloat16(v1);
                    }
                }
        }
        return;
    }

    #pragma unroll
    for (int i = 0; i < 2; i++) {
        #pragma unroll
        for (int j = 0; j < 4; j++) {
            int rbase = tok0 + warp_m * 32 + i * 16 + (lane >> 2);
            int cbase = f0 + warp_n * 32 + j * 8 + (lane & 3) * 2;
            #pragma unroll
            for (int h = 0; h < 2; h++) {
                int n = rbase + h * 8;
                float v0 = acc[i][j][h * 2 + 0];
                float v1 = acc[i][j][h * 2 + 1];
                if (bias) { v0 += bias[cbase]; v1 += bias[cbase + 1]; }
                if (MODE == 1) {
                    v0 = 0.5f * v0 * (1.0f + erff(v0 * 0.70710678118654752f));
                    v1 = 0.5f * v1 * (1.0f + erff(v1 * 0.70710678118654752f));
                }
                if (res) {
                    float2 rv = *(const float2*)(res + (size_t)n * M + cbase);
                    v0 += rv.x; v1 += rv.y;
                }
                if (outF) {
                    float2 o; o.x = v0; o.y = v1;
                    *(float2*)(outF + (size_t)n * M + cbase) = o;
                }
                if (outH) {
                    *(__nv_bfloat162*)(outH + (size_t)n * M + cbase) =
                        __floats2bfloat162_rn(v0, v1);
                }
            }
        }
    }
}

// ---------------------------------------------------------------------------
// Tensor-core flash attention with fused LePE, window-major bf16 operands.
// ldmatrix B-fragments; 3 blocks/SM.
// ---------------------------------------------------------------------------
#define KPIT 24
#define VPIT 520

__device__ __forceinline__ unsigned packbf(float a, float b) {
    __nv_bfloat162 t = __floats2bfloat162_rn(a, b);
    return *(unsigned*)&t;
}
__device__ __forceinline__ float ex2(float x) {
    float y; asm("ex2.approx.ftz.f32 %0, %1;" : "=f"(y) : "f"(x)); return y;
}

template<int Hsp, int Wsp, int nHb, int nWb, int brOff>
__device__ __forceinline__ void attn_body(
        __nv_bfloat16 (*sK)[KPIT], __nv_bfloat16 (*sVT)[VPIT],
        float (*sCW)[27], float* sCB,
        const float* __restrict__ cw, const float* __restrict__ cb,
        __nv_bfloat16* __restrict__ att, int bw) {
    constexpr int HW = Hsp * Wsp;   // 128
    constexpr int BR = (brOff == 0) ? 0 : 1;

    int tid = threadIdx.x, lane = tid & 31, wid = tid >> 5;
    int head = blockIdx.y;

    int wb = bw % nWb;
    int t1 = bw / nWb;
    int hb = t1 % nHb; t1 /= nHb;
    int tb = t1 & 1;
    int bq = t1 >> 1;
    int baseTok = bq * LL + tb * TSP * (RES * RES) + hb * Hsp * RES + wb * Wsp;
    int cbase = brOff + head * HD;

    for (int e = tid; e < HD * 27; e += 256) {
        int d = e / 27, k = e - d * 27;
        sCW[d][k] = cw[(head * HD + d) * 27 + k];
    }
    if (tid < HD) sCB[tid] = cb[head * HD + tid];

    size_t hbase = ((size_t)((BR * NWIN + bw) * NH + head)) << 13;

    // stage K and V^T: pure vector copies
    const uint4* kp = (const uint4*)(g_kw + hbase);
    #pragma unroll
    for (int p = 0; p < 4; p++) {
        int e = tid + p * 256;
        uint4 v = kp[e];
        int j = e >> 1, seg = (e & 1) * 8;
        *(uint4*)(&sK[j][seg]) = v;
    }
    const uint4* vp = (const uint4*)(g_vt + hbase);
    #pragma unroll
    for (int p = 0; p < 4; p++) {
        int e = tid + p * 256;
        uint4 v = vp[e];
        int d = e >> 6, j8 = (e & 63) * 8;
        *(uint4*)(&sVT[d][j8]) = v;
    }

    // Q fragment (pre-scaled bf16, window-major)
    int qr = lane >> 2, kc = (lane & 3) * 2;
    int qbase = blockIdx.x * 128 + wid * 16;
    unsigned qa[4];
    #pragma unroll
    for (int h = 0; h < 2; h++) {
        int j = qbase + qr + h * 8;
        const __nv_bfloat16* qp = g_qw + hbase + j * HD;
        qa[h]     = *(const unsigned*)(qp + kc);
        qa[2 + h] = *(const unsigned*)(qp + kc + 8);
    }
    __syncthreads();

    // ldmatrix base addresses (lanes 0-7: matrix0 rows, 8-15: matrix1 = +8 cols)
    unsigned kaddr0 = (unsigned)__cvta_generic_to_shared(&sK[lane & 7][0])
                      + ((lane >> 3) & 1) * 16;
    unsigned vaddr0 = (unsigned)__cvta_generic_to_shared(&sVT[lane & 7][0])
                      + ((lane >> 3) & 1) * 16;

    float O[2][4];
    #pragma unroll
    for (int v = 0; v < 2; v++)
        #pragma unroll
        for (int r = 0; r < 4; r++) O[v][r] = 0.0f;
    float m0 = -1e30f, m1 = -1e30f, l0 = 0.0f, l1 = 0.0f;

    #pragma unroll 1
    for (int ch = 0; ch < 8; ch++) {
        int n0 = ch * 64;
        float S[8][4];
        #pragma unroll
        for (int t = 0; t < 8; t++) {
            S[t][0] = S[t][1] = S[t][2] = S[t][3] = 0.0f;
            unsigned b0, b1;
            unsigned addr = kaddr0 + (unsigned)((n0 + t * 8) * (KPIT * 2));
            asm volatile("ldmatrix.sync.aligned.m8n8.x2.shared.b16 {%0,%1}, [%2];"
                         : "=r"(b0), "=r"(b1) : "r"(addr));
            asm volatile(
                "mma.sync.aligned.m16n8k16.row.col.f32.bf16.bf16.f32 "
                "{%0,%1,%2,%3}, {%4,%5,%6,%7}, {%8,%9}, {%0,%1,%2,%3};"
                : "+f"(S[t][0]), "+f"(S[t][1]), "+f"(S[t][2]), "+f"(S[t][3])
                : "r"(qa[0]), "r"(qa[1]), "r"(qa[2]), "r"(qa[3]),
                  "r"(b0), "r"(b1));
        }
        float mx0 = -1e30f, mx1 = -1e30f;
        #pragma unroll
        for (int t = 0; t < 8; t++) {
            mx0 = fmaxf(mx0, fmaxf(S[t][0], S[t][1]));
            mx1 = fmaxf(mx1, fmaxf(S[t][2], S[t][3]));
        }
        mx0 = fmaxf(mx0, __shfl_xor_sync(0xffffffffu, mx0, 1));
        mx0 = fmaxf(mx0, __shfl_xor_sync(0xffffffffu, mx0, 2));
        mx1 = fmaxf(mx1, __shfl_xor_sync(0xffffffffu, mx1, 1));
        mx1 = fmaxf(mx1, __shfl_xor_sync(0xffffffffu, mx1, 2));
        float nm0 = fmaxf(m0, mx0), nm1 = fmaxf(m1, mx1);
        float c0 = ex2(m0 - nm0), c1 = ex2(m1 - nm1);
        m0 = nm0; m1 = nm1;
        l0 *= c0; l1 *= c1;
        #pragma unroll
        for (int v = 0; v < 2; v++) {
            O[v][0] *= c0; O[v][1] *= c0; O[v][2] *= c1; O[v][3] *= c1;
        }
        #pragma unroll
        for (int t = 0; t < 8; t++) {
            S[t][0] = ex2(S[t][0] - m0);
            S[t][1] = ex2(S[t][1] - m0);
            S[t][2] = ex2(S[t][2] - m1);
            S[t][3] = ex2(S[t][3] - m1);
            l0 += S[t][0] + S[t][1];
            l1 += S[t][2] + S[t][3];
        }
        #pragma unroll
        for (int kk = 0; kk < 4; kk++) {
            unsigned a0 = packbf(S[2 * kk][0], S[2 * kk][1]);
            unsigned a1 = packbf(S[2 * kk][2], S[2 * kk][3]);
            unsigned a2 = packbf(S[2 * kk + 1][0], S[2 * kk + 1][1]);
            unsigned a3 = packbf(S[2 * kk + 1][2], S[2 * kk + 1][3]);
            #pragma unroll
            for (int v = 0; v < 2; v++) {
                unsigned b0, b1;
                unsigned addr = vaddr0 + (unsigned)(v * (8 * VPIT * 2) + (n0 + kk * 16) * 2);
                asm volatile("ldmatrix.sync.aligned.m8n8.x2.shared.b16 {%0,%1}, [%2];"
                             : "=r"(b0), "=r"(b1) : "r"(addr));
                asm volatile(
                    "mma.sync.aligned.m16n8k16.row.col.f32.bf16.bf16.f32 "
                    "{%0,%1,%2,%3}, {%4,%5,%6,%7}, {%8,%9}, {%0,%1,%2,%3};"
                    : "+f"(O[v][0]), "+f"(O[v][1]), "+f"(O[v][2]), "+f"(O[v][3])
                    : "r"(a0), "r"(a1), "r"(a2), "r"(a3),
                      "r"(b0), "r"(b1));
            }
        }
    }

    l0 += __shfl_xor_sync(0xffffffffu, l0, 1);
    l0 += __shfl_xor_sync(0xffffffffu, l0, 2);
    l1 += __shfl_xor_sync(0xffffffffu, l1, 1);
    l1 += __shfl_xor_sync(0xffffffffu, l1, 2);
    float inv0 = 1.0f / l0, inv1 = 1.0f / l1;

    // epilogue: O/l + fused LePE conv, store bf16 (token-major for proj GEMM)
    #pragma unroll
    for (int h = 0; h < 2; h++) {
        int j = qbase + qr + h * 8;
        int ts = j / HW;
        int rem = j - ts * HW;
        int hs = rem / Wsp;
        int ws = rem - hs * Wsp;
        int n = baseTok + ts * (RES * RES) + hs * RES + ws;
        float inv = h ? inv1 : inv0;

        int d0 = kc, d1 = kc + 1, d2 = 8 + kc, d3 = 9 + kc;
        float acc0 = sCB[d0], acc1 = sCB[d1], acc2 = sCB[d2], acc3 = sCB[d3];
        #pragma unroll
        for (int kt = 0; kt < 3; kt++) {
            int ttc = ts + kt - 1;
            if ((unsigned)ttc >= (unsigned)TSP) continue;
            #pragma unroll
            for (int kh = 0; kh < 3; kh++) {
                int hh = hs + kh - 1;
                if ((unsigned)hh >= (unsigned)Hsp) continue;
                #pragma unroll
                for (int kw2 = 0; kw2 < 3; kw2++) {
                    int ww = ws + kw2 - 1;
                    if ((unsigned)ww >= (unsigned)Wsp) continue;
                    int jp = ttc * HW + hh * Wsp + ww;
                    int widx = kt * 9 + kh * 3 + kw2;
                    acc0 += sCW[d0][widx] * __bfloat162float(sVT[d0][jp]);
                    acc1 += sCW[d1][widx] * __bfloat162float(sVT[d1][jp]);
                    acc2 += sCW[d2][widx] * __bfloat162float(sVT[d2][jp]);
                    acc3 += sCW[d3][widx] * __bfloat162float(sVT[d3][jp]);
                }
            }
        }
        float o0 = O[0][h * 2 + 0] * inv + acc0;
        float o1 = O[0][h * 2 + 1] * inv + acc1;
        float o2 = O[1][h * 2 + 0] * inv + acc2;
        float o3 = O[1][h * 2 + 1] * inv + acc3;
        __nv_bfloat16* ap = att + (size_t)n * CC + cbase;
        *(__nv_bfloat162*)(ap + kc)     = __floats2bfloat162_rn(o0, o1);
        *(__nv_bfloat162*)(ap + 8 + kc) = __floats2bfloat162_rn(o2, o3);
    }
}

__global__ __launch_bounds__(256, 3) void attn_mma_all(
        __nv_bfloat16* __restrict__ att,
        const float* __restrict__ cw0, const float* __restrict__ cb0,
        const float* __restrict__ cw1, const float* __restrict__ cb1) {
    __shared__ __nv_bfloat16 sK[WIN][KPIT];
    __shared__ __nv_bfloat16 sVT[HD][VPIT];
    __shared__ float sCW[HD][27];
    __shared__ float sCB[HD];

    int bz = blockIdx.z;
    if (bz < NWIN) {
        attn_body<RES, TSP, 1, 8, 0>(sK, sVT, sCW, sCB, cw0, cb0, att, bz);
    } else {
        attn_body<TSP, RES, 8, 1, HCH>(sK, sVT, sCW, sCB, cw1, cb1, att, bz - NWIN);
    }
}

// ---------------------------------------------------------------------------
// Launch
// ---------------------------------------------------------------------------
extern "C" void kernel_launch(void* const* d_in, const int* in_sizes, int n_in,
                              void* d_out, int out_size) {
    const float* x       = (const float*)d_in[0];
    const float* norm1_w = (const float*)d_in[1];
    const float* norm1_b = (const float*)d_in[2];
    const float* qkv_w   = (const float*)d_in[3];
    const float* conv_w0 = (const float*)d_in[4];
    const float* conv_b0 = (const float*)d_in[5];
    const float* conv_w1 = (const float*)d_in[6];
    const float* conv_b1 = (const float*)d_in[7];
    const float* proj_w  = (const float*)d_in[8];
    const float* proj_b  = (const float*)d_in[9];
    const float* norm2_w = (const float*)d_in[10];
    const float* norm2_b = (const float*)d_in[11];
    const float* fc1_w   = (const float*)d_in[12];
    const float* fc1_b   = (const float*)d_in[13];
    const float* fc2_w   = (const float*)d_in[14];
    const float* fc2_b   = (const float*)d_in[15];
    float* out = (float*)d_out;

    __nv_bfloat16 *img, *att, *y1, *hbuf, *qkvw, *projw, *fc1w, *fc2w;
    float *xa;
    cudaGetSymbolAddress((void**)&img,   g_img);
    cudaGetSymbolAddress((void**)&att,   g_att);
    cudaGetSymbolAddress((void**)&xa,    g_xa);
    cudaGetSymbolAddress((void**)&y1,    g_y1);
    cudaGetSymbolAddress((void**)&hbuf,  g_h);
    cudaGetSymbolAddress((void**)&qkvw,  g_qkvw);
    cudaGetSymbolAddress((void**)&projw, g_projw);
    cudaGetSymbolAddress((void**)&fc1w,  g_fc1w);
    cudaGetSymbolAddress((void**)&fc2w,  g_fc2w);

    // 0. weight conversion
    cvt4_kernel<<<(HID * CC + 255) / 256, 256>>>(
        qkv_w, qkvw, 3 * CC * CC,
        proj_w, projw, CC * CC,
        fc1_w, fc1w, HID * CC,
        fc2_w, fc2w, CC * HID);

    // 1. LN1 -> bf16
    ln_kernel<<<NTOK / 8, 256>>>(x, norm1_w, norm1_b, img);

    // 2. QKV GEMM, epilogue scatters window-major bf16 q/k/v
    gemm_mma<2><<<dim3(NTOK / GBM, (3 * CC) / GBN), 256>>>(
        img, qkvw, nullptr, nullptr, nullptr, nullptr, NTOK, CC, 3 * CC);

    // 3. Attention + fused LePE, both branches in one launch
    attn_mma_all<<<dim3(4, NH, 2 * NWIN), 256>>>(att, conv_w0, conv_b0, conv_w1, conv_b1);

    // 4. proj + bias + residual(x) -> xa
    gemm_mma<0><<<dim3(NTOK / GBM, CC / GBN), 256>>>(
        att, projw, proj_b, x, xa, nullptr, NTOK, CC, CC);

    // 5. LN2 -> bf16
    ln_kernel<<<NTOK / 8, 256>>>(xa, norm2_w, norm2_b, y1);

    // 6. FC1 + bias + GELU -> bf16
    gemm_mma<1><<<dim3(NTOK / GBM, HID / GBN), 256>>>(
        y1, fc1w, fc1_b, nullptr, nullptr, hbuf, NTOK, CC, HID);

    // 7. FC2 + bias + residual(xa) -> out
    gemm_mma<0><<<dim3(NTOK / GBM, CC / GBN), 256>>>(
        hbuf, fc2w, fc2_b, xa, out, nullptr, NTOK, HID, CC);
}

// round 16
// speedup vs baseline: 1.3725x; 1.3725x over previous
#include <cuda_runtime.h>
#include <cuda_bf16.h>
#include <math.h>

// ---------------------------------------------------------------------------
// Problem constants
// ---------------------------------------------------------------------------
#define BB    4
#define TT    8
#define RES   32
#define CC    128
#define LL    (TT * RES * RES)        // 8192
#define NTOK  (BB * LL)               // 32768
#define HID   (4 * CC)                // 512
#define TSP   4
#define WIN   512
#define NWIN  64
#define NH    4
#define HD    16
#define HCH   64

#define QSCALE 0.36067376022224085f   // 0.25 * log2(e)

// ---------------------------------------------------------------------------
// Scratch
// ---------------------------------------------------------------------------
__device__ __nv_bfloat16 g_img[(size_t)NTOK * CC];
__device__ __nv_bfloat16 g_att[(size_t)NTOK * CC];
__device__ float         g_xa [(size_t)NTOK * CC];
__device__ __nv_bfloat16 g_y1 [(size_t)NTOK * CC];
__device__ __nv_bfloat16 g_h  [(size_t)NTOK * HID];
__device__ __nv_bfloat16 g_qkvw[(size_t)3 * CC * CC];
__device__ __nv_bfloat16 g_projw[(size_t)CC * CC];
__device__ __nv_bfloat16 g_fc1w[(size_t)HID * CC];
__device__ __nv_bfloat16 g_fc2w[(size_t)CC * HID];
// window-major attention operands: [branch][win][head][j][d] (q scaled)
__device__ __nv_bfloat16 g_qw[(size_t)2 * NWIN * NH * WIN * HD];
__device__ __nv_bfloat16 g_kw[(size_t)2 * NWIN * NH * WIN * HD];
// transposed V: [branch][win][head][d][j]
__device__ __nv_bfloat16 g_vt[(size_t)2 * NWIN * NH * HD * WIN];

// ---------------------------------------------------------------------------
// fp32 -> bf16 weight conversion
// ---------------------------------------------------------------------------
__global__ void cvt4_kernel(const float* __restrict__ s0, __nv_bfloat16* __restrict__ d0, int n0,
                            const float* __restrict__ s1, __nv_bfloat16* __restrict__ d1, int n1,
                            const float* __restrict__ s2, __nv_bfloat16* __restrict__ d2, int n2,
                            const float* __restrict__ s3, __nv_bfloat16* __restrict__ d3, int n3) {
    int i = blockIdx.x * blockDim.x + threadIdx.x;
    if (i < n0) d0[i] = __float2bfloat16(s0[i]);
    if (i < n1) d1[i] = __float2bfloat16(s1[i]);
    if (i < n2) d2[i] = __float2bfloat16(s2[i]);
    if (i < n3) d3[i] = __float2bfloat16(s3[i]);
}

// ---------------------------------------------------------------------------
// LayerNorm: one warp per token; writes bf16
// ---------------------------------------------------------------------------
__global__ void ln_kernel(const float* __restrict__ x, const float* __restrict__ w,
                          const float* __restrict__ b, __nv_bfloat16* __restrict__ out) {
    int gw   = (blockIdx.x * blockDim.x + threadIdx.x) >> 5;
    int lane = threadIdx.x & 31;
    if (gw >= NTOK) return;
    float4 v = ((const float4*)(x + (size_t)gw * CC))[lane];
    float s = v.x + v.y + v.z + v.w;
    #pragma unroll
    for (int o = 16; o; o >>= 1) s += __shfl_xor_sync(0xffffffffu, s, o);
    float mu = s * (1.0f / CC);
    float dx = v.x - mu, dy = v.y - mu, dz = v.z - mu, dw = v.w - mu;
    float s2 = dx * dx + dy * dy + dz * dz + dw * dw;
    #pragma unroll
    for (int o = 16; o; o >>= 1) s2 += __shfl_xor_sync(0xffffffffu, s2, o);
    float rstd = rsqrtf(s2 * (1.0f / CC) + 1e-5f);
    float4 w4 = ((const float4*)w)[lane];
    float4 b4 = ((const float4*)b)[lane];
    float ox = dx * rstd * w4.x + b4.x;
    float oy = dy * rstd * w4.y + b4.y;
    float oz = dz * rstd * w4.z + b4.z;
    float ow = dw * rstd * w4.w + b4.w;
    __nv_bfloat162* op = (__nv_bfloat162*)(out + (size_t)gw * CC);
    op[lane * 2]     = __floats2bfloat162_rn(ox, oy);
    op[lane * 2 + 1] = __floats2bfloat162_rn(oz, ow);
}

// ---------------------------------------------------------------------------
// bf16 MMA GEMM (R11 synchronous version — the cp.async variant regressed).
// MODE: 0 = plain/residual, 1 = +gelu, 2 = qkv window-scatter
// ---------------------------------------------------------------------------
#define GBM 128
#define GBN 64
#define GBK 32
#define APIT 40

template<int MODE>
__global__ void gemm_mma(const __nv_bfloat16* __restrict__ A, const __nv_bfloat16* __restrict__ W,
                         const float* __restrict__ bias, const float* __restrict__ res,
                         float* __restrict__ outF, __nv_bfloat16* __restrict__ outH,
                         int N, int K, int M) {
    __shared__ __nv_bfloat16 sA[GBM][APIT];
    __shared__ __nv_bfloat16 sW[GBN][APIT];
    int tid = threadIdx.x;
    int wid = tid >> 5, lane = tid & 31;
    int warp_m = wid >> 1, warp_n = wid & 1;
    int tok0 = blockIdx.x * GBM;
    int f0   = blockIdx.y * GBN;

    float acc[2][4][4];
    #pragma unroll
    for (int i = 0; i < 2; i++)
        #pragma unroll
        for (int j = 0; j < 4; j++)
            #pragma unroll
            for (int r = 0; r < 4; r++) acc[i][j][r] = 0.0f;

    for (int k0 = 0; k0 < K; k0 += GBK) {
        #pragma unroll
        for (int p = 0; p < 2; p++) {
            int idx = tid + p * 256;
            int row = idx >> 2, seg = idx & 3;
            uint4 v = *(const uint4*)(A + (size_t)(tok0 + row) * K + k0 + seg * 8);
            *(uint4*)(&sA[row][seg * 8]) = v;
        }
        {
            int row = tid >> 2, seg = tid & 3;
            uint4 v = *(const uint4*)(W + (size_t)(f0 + row) * K + k0 + seg * 8);
            *(uint4*)(&sW[row][seg * 8]) = v;
        }
        __syncthreads();
        #pragma unroll
        for (int kk = 0; kk < GBK; kk += 16) {
            unsigned afrag[2][4], bfrag[4][2];
            int rr = (lane >> 2);
            int cc2 = kk + (lane & 3) * 2;
            #pragma unroll
            for (int i = 0; i < 2; i++) {
                int r = warp_m * 32 + i * 16 + rr;
                afrag[i][0] = *(const unsigned*)(&sA[r][cc2]);
                afrag[i][1] = *(const unsigned*)(&sA[r + 8][cc2]);
                afrag[i][2] = *(const unsigned*)(&sA[r][cc2 + 8]);
                afrag[i][3] = *(const unsigned*)(&sA[r + 8][cc2 + 8]);
            }
            #pragma unroll
            for (int j = 0; j < 4; j++) {
                int n = warp_n * 32 + j * 8 + rr;
                bfrag[j][0] = *(const unsigned*)(&sW[n][cc2]);
                bfrag[j][1] = *(const unsigned*)(&sW[n][cc2 + 8]);
            }
            #pragma unroll
            for (int i = 0; i < 2; i++)
                #pragma unroll
                for (int j = 0; j < 4; j++)
                    asm volatile(
                        "mma.sync.aligned.m16n8k16.row.col.f32.bf16.bf16.f32 "
                        "{%0,%1,%2,%3}, {%4,%5,%6,%7}, {%8,%9}, {%0,%1,%2,%3};"
                        : "+f"(acc[i][j][0]), "+f"(acc[i][j][1]),
                          "+f"(acc[i][j][2]), "+f"(acc[i][j][3])
                        : "r"(afrag[i][0]), "r"(afrag[i][1]),
                          "r"(afrag[i][2]), "r"(afrag[i][3]),
                          "r"(bfrag[j][0]), "r"(bfrag[j][1]));
        }
        __syncthreads();
    }

    if (MODE == 2) {
        // decode 4 distinct rows (token -> both-branch window coords)
        int bw0[2][2], bw1[2][2], j0[2][2], j1[2][2];
        #pragma unroll
        for (int i = 0; i < 2; i++)
            #pragma unroll
            for (int h = 0; h < 2; h++) {
                int n = tok0 + warp_m * 32 + i * 16 + (lane >> 2) + h * 8;
                int bq = n >> 13, l = n & 8191;
                int tc = l >> 10, hh = (l >> 5) & 31, ww = l & 31;
                int bq2 = bq * 2 + (tc >> 2), ts = tc & 3;
                bw0[i][h] = bq2 * 8 + (ww >> 2);
                j0[i][h]  = ts * 128 + hh * 4 + (ww & 3);
                bw1[i][h] = bq2 * 8 + (hh >> 2);
                j1[i][h]  = ts * 128 + (hh & 3) * 32 + ww;
            }
        #pragma unroll
        for (int j = 0; j < 4; j++) {
            int m = f0 + warp_n * 32 + j * 8 + (lane & 3) * 2;
            int part = m >> 7, mm = m & 127;
            int br = (mm >> 6) & 1, head = (mm >> 4) & 3, d = mm & 15;
            int hb = (br * NWIN * NH) + head;
            #pragma unroll
            for (int i = 0; i < 2; i++)
                #pragma unroll
                for (int h = 0; h < 2; h++) {
                    int bw = br ? bw1[i][h] : bw0[i][h];
                    int jj = br ? j1[i][h] : j0[i][h];
                    size_t base = ((size_t)(hb + bw * NH)) << 13;
                    float v0 = acc[i][j][h * 2 + 0];
                    float v1 = acc[i][j][h * 2 + 1];
                    if (part == 0) {
                        *(__nv_bfloat162*)(g_qw + base + jj * HD + d) =
                            __floats2bfloat162_rn(v0 * QSCALE, v1 * QSCALE);
                    } else if (part == 1) {
                        *(__nv_bfloat162*)(g_kw + base + jj * HD + d) =
                            __floats2bfloat162_rn(v0, v1);
                    } else {
                        g_vt[base + (size_t)d * WIN + jj]       = __float2bfloat16(v0);
                        g_vt[base + (size_t)(d + 1) * WIN + jj] = __float2bfloat16(v1);
                    }
                }
        }
        return;
    }

    #pragma unroll
    for (int i = 0; i < 2; i++) {
        #pragma unroll
        for (int j = 0; j < 4; j++) {
            int rbase = tok0 + warp_m * 32 + i * 16 + (lane >> 2);
            int cbase = f0 + warp_n * 32 + j * 8 + (lane & 3) * 2;
            #pragma unroll
            for (int h = 0; h < 2; h++) {
                int n = rbase + h * 8;
                float v0 = acc[i][j][h * 2 + 0];
                float v1 = acc[i][j][h * 2 + 1];
                if (bias) { v0 += bias[cbase]; v1 += bias[cbase + 1]; }
                if (MODE == 1) {
                    v0 = 0.5f * v0 * (1.0f + erff(v0 * 0.70710678118654752f));
                    v1 = 0.5f * v1 * (1.0f + erff(v1 * 0.70710678118654752f));
                }
                if (res) {
                    float2 rv = *(const float2*)(res + (size_t)n * M + cbase);
                    v0 += rv.x; v1 += rv.y;
                }
                if (outF) {
                    float2 o; o.x = v0; o.y = v1;
                    *(float2*)(outF + (size_t)n * M + cbase) = o;
                }
                if (outH) {
                    *(__nv_bfloat162*)(outH + (size_t)n * M + cbase) =
                        __floats2bfloat162_rn(v0, v1);
                }
            }
        }
    }
}

// ---------------------------------------------------------------------------
// Tensor-core flash attention with fused LePE, window-major bf16 operands.
// ONE block per (window, head): stages K/V^T once, loops over 4 q-tiles.
// ---------------------------------------------------------------------------
#define KPIT 24
#define VPIT 520

__device__ __forceinline__ unsigned packbf(float a, float b) {
    __nv_bfloat162 t = __floats2bfloat162_rn(a, b);
    return *(unsigned*)&t;
}
__device__ __forceinline__ float ex2(float x) {
    float y; asm("ex2.approx.ftz.f32 %0, %1;" : "=f"(y) : "f"(x)); return y;
}

template<int Hsp, int Wsp, int nHb, int nWb, int brOff>
__device__ __forceinline__ void attn_body(
        __nv_bfloat16 (*sK)[KPIT], __nv_bfloat16 (*sVT)[VPIT],
        float (*sCW)[27], float* sCB,
        const float* __restrict__ cw, const float* __restrict__ cb,
        __nv_bfloat16* __restrict__ att, int bw) {
    constexpr int HW = Hsp * Wsp;   // 128
    constexpr int BR = (brOff == 0) ? 0 : 1;

    int tid = threadIdx.x, lane = tid & 31, wid = tid >> 5;
    int head = blockIdx.x;

    int wb = bw % nWb;
    int t1 = bw / nWb;
    int hb = t1 % nHb; t1 /= nHb;
    int tb = t1 & 1;
    int bq = t1 >> 1;
    int baseTok = bq * LL + tb * TSP * (RES * RES) + hb * Hsp * RES + wb * Wsp;
    int cbase = brOff + head * HD;

    for (int e = tid; e < HD * 27; e += 256) {
        int d = e / 27, k = e - d * 27;
        sCW[d][k] = cw[(head * HD + d) * 27 + k];
    }
    if (tid < HD) sCB[tid] = cb[head * HD + tid];

    size_t hbase = ((size_t)((BR * NWIN + bw) * NH + head)) << 13;

    // stage K and V^T once: pure vector copies
    const uint4* kp = (const uint4*)(g_kw + hbase);
    #pragma unroll
    for (int p = 0; p < 4; p++) {
        int e = tid + p * 256;
        uint4 v = kp[e];
        int j = e >> 1, seg = (e & 1) * 8;
        *(uint4*)(&sK[j][seg]) = v;
    }
    const uint4* vp = (const uint4*)(g_vt + hbase);
    #pragma unroll
    for (int p = 0; p < 4; p++) {
        int e = tid + p * 256;
        uint4 v = vp[e];
        int d = e >> 6, j8 = (e & 63) * 8;
        *(uint4*)(&sVT[d][j8]) = v;
    }
    __syncthreads();

    int qr = lane >> 2, kc = (lane & 3) * 2;

    // loop over the 4 q-tiles (smem read-only from here: no syncs needed)
    #pragma unroll 1
    for (int qb = 0; qb < 4; qb++) {
        int qbase = qb * 128 + wid * 16;
        unsigned qa[4];
        #pragma unroll
        for (int h = 0; h < 2; h++) {
            int j = qbase + qr + h * 8;
            const __nv_bfloat16* qp = g_qw + hbase + j * HD;
            qa[h]     = *(const unsigned*)(qp + kc);
            qa[2 + h] = *(const unsigned*)(qp + kc + 8);
        }

        float O[2][4];
        #pragma unroll
        for (int v = 0; v < 2; v++)
            #pragma unroll
            for (int r = 0; r < 4; r++) O[v][r] = 0.0f;
        float m0 = -1e30f, m1 = -1e30f, l0 = 0.0f, l1 = 0.0f;

        #pragma unroll 1
        for (int ch = 0; ch < 8; ch++) {
            int n0 = ch * 64;
            float S[8][4];
            #pragma unroll
            for (int t = 0; t < 8; t++) {
                S[t][0] = S[t][1] = S[t][2] = S[t][3] = 0.0f;
                unsigned b0 = *(const unsigned*)(&sK[n0 + t * 8 + qr][kc]);
                unsigned b1 = *(const unsigned*)(&sK[n0 + t * 8 + qr][kc + 8]);
                asm volatile(
                    "mma.sync.aligned.m16n8k16.row.col.f32.bf16.bf16.f32 "
                    "{%0,%1,%2,%3}, {%4,%5,%6,%7}, {%8,%9}, {%0,%1,%2,%3};"
                    : "+f"(S[t][0]), "+f"(S[t][1]), "+f"(S[t][2]), "+f"(S[t][3])
                    : "r"(qa[0]), "r"(qa[1]), "r"(qa[2]), "r"(qa[3]),
                      "r"(b0), "r"(b1));
            }
            float mx0 = -1e30f, mx1 = -1e30f;
            #pragma unroll
            for (int t = 0; t < 8; t++) {
                mx0 = fmaxf(mx0, fmaxf(S[t][0], S[t][1]));
                mx1 = fmaxf(mx1, fmaxf(S[t][2], S[t][3]));
            }
            mx0 = fmaxf(mx0, __shfl_xor_sync(0xffffffffu, mx0, 1));
            mx0 = fmaxf(mx0, __shfl_xor_sync(0xffffffffu, mx0, 2));
            mx1 = fmaxf(mx1, __shfl_xor_sync(0xffffffffu, mx1, 1));
            mx1 = fmaxf(mx1, __shfl_xor_sync(0xffffffffu, mx1, 2));
            float nm0 = fmaxf(m0, mx0), nm1 = fmaxf(m1, mx1);
            float c0 = ex2(m0 - nm0), c1 = ex2(m1 - nm1);
            m0 = nm0; m1 = nm1;
            l0 *= c0; l1 *= c1;
            #pragma unroll
            for (int v = 0; v < 2; v++) {
                O[v][0] *= c0; O[v][1] *= c0; O[v][2] *= c1; O[v][3] *= c1;
            }
            #pragma unroll
            for (int t = 0; t < 8; t++) {
                S[t][0] = ex2(S[t][0] - m0);
                S[t][1] = ex2(S[t][1] - m0);
                S[t][2] = ex2(S[t][2] - m1);
                S[t][3] = ex2(S[t][3] - m1);
                l0 += S[t][0] + S[t][1];
                l1 += S[t][2] + S[t][3];
            }
            #pragma unroll
            for (int kk = 0; kk < 4; kk++) {
                unsigned a0 = packbf(S[2 * kk][0], S[2 * kk][1]);
                unsigned a1 = packbf(S[2 * kk][2], S[2 * kk][3]);
                unsigned a2 = packbf(S[2 * kk + 1][0], S[2 * kk + 1][1]);
                unsigned a3 = packbf(S[2 * kk + 1][2], S[2 * kk + 1][3]);
                int keyc = n0 + kk * 16 + kc;
                #pragma unroll
                for (int v = 0; v < 2; v++) {
                    unsigned b0 = *(const unsigned*)(&sVT[v * 8 + qr][keyc]);
                    unsigned b1 = *(const unsigned*)(&sVT[v * 8 + qr][keyc + 8]);
                    asm volatile(
                        "mma.sync.aligned.m16n8k16.row.col.f32.bf16.bf16.f32 "
                        "{%0,%1,%2,%3}, {%4,%5,%6,%7}, {%8,%9}, {%0,%1,%2,%3};"
                        : "+f"(O[v][0]), "+f"(O[v][1]), "+f"(O[v][2]), "+f"(O[v][3])
                        : "r"(a0), "r"(a1), "r"(a2), "r"(a3),
                          "r"(b0), "r"(b1));
                }
            }
        }

        l0 += __shfl_xor_sync(0xffffffffu, l0, 1);
        l0 += __shfl_xor_sync(0xffffffffu, l0, 2);
        l1 += __shfl_xor_sync(0xffffffffu, l1, 1);
        l1 += __shfl_xor_sync(0xffffffffu, l1, 2);
        float inv0 = 1.0f / l0, inv1 = 1.0f / l1;

        // epilogue: O/l + fused LePE conv, store bf16 (token-major)
        #pragma unroll
        for (int h = 0; h < 2; h++) {
            int j = qbase + qr + h * 8;
            int ts = j / HW;
            int rem = j - ts * HW;
            int hs = rem / Wsp;
            int ws = rem - hs * Wsp;
            int n = baseTok + ts * (RES * RES) + hs * RES + ws;
            float inv = h ? inv1 : inv0;

            int d0 = kc, d1 = kc + 1, d2 = 8 + kc, d3 = 9 + kc;
            float acc0 = sCB[d0], acc1 = sCB[d1], acc2 = sCB[d2], acc3 = sCB[d3];
            #pragma unroll
            for (int kt = 0; kt < 3; kt++) {
                int ttc = ts + kt - 1;
                if ((unsigned)ttc >= (unsigned)TSP) continue;
                #pragma unroll
                for (int kh = 0; kh < 3; kh++) {
                    int hh = hs + kh - 1;
                    if ((unsigned)hh >= (unsigned)Hsp) continue;
                    #pragma unroll
                    for (int kw2 = 0; kw2 < 3; kw2++) {
                        int ww = ws + kw2 - 1;
                        if ((unsigned)ww >= (unsigned)Wsp) continue;
                        int jp = ttc * HW + hh * Wsp + ww;
                        int widx = kt * 9 + kh * 3 + kw2;
                        acc0 += sCW[d0][widx] * __bfloat162float(sVT[d0][jp]);
                        acc1 += sCW[d1][widx] * __bfloat162float(sVT[d1][jp]);
                        acc2 += sCW[d2][widx] * __bfloat162float(sVT[d2][jp]);
                        acc3 += sCW[d3][widx] * __bfloat162float(sVT[d3][jp]);
                    }
                }
            }
            float o0 = O[0][h * 2 + 0] * inv + acc0;
            float o1 = O[0][h * 2 + 1] * inv + acc1;
            float o2 = O[1][h * 2 + 0] * inv + acc2;
            float o3 = O[1][h * 2 + 1] * inv + acc3;
            __nv_bfloat16* ap = att + (size_t)n * CC + cbase;
            *(__nv_bfloat162*)(ap + kc)     = __floats2bfloat162_rn(o0, o1);
            *(__nv_bfloat162*)(ap + 8 + kc) = __floats2bfloat162_rn(o2, o3);
        }
    }
}

__global__ __launch_bounds__(256, 2) void attn_mma_all(
        __nv_bfloat16* __restrict__ att,
        const float* __restrict__ cw0, const float* __restrict__ cb0,
        const float* __restrict__ cw1, const float* __restrict__ cb1) {
    __shared__ __nv_bfloat16 sK[WIN][KPIT];
    __shared__ __nv_bfloat16 sVT[HD][VPIT];
    __shared__ float sCW[HD][27];
    __shared__ float sCB[HD];

    int bz = blockIdx.y;
    if (bz < NWIN) {
        attn_body<RES, TSP, 1, 8, 0>(sK, sVT, sCW, sCB, cw0, cb0, att, bz);
    } else {
        attn_body<TSP, RES, 8, 1, HCH>(sK, sVT, sCW, sCB, cw1, cb1, att, bz - NWIN);
    }
}

// ---------------------------------------------------------------------------
// Launch
// ---------------------------------------------------------------------------
extern "C" void kernel_launch(void* const* d_in, const int* in_sizes, int n_in,
                              void* d_out, int out_size) {
    const float* x       = (const float*)d_in[0];
    const float* norm1_w = (const float*)d_in[1];
    const float* norm1_b = (const float*)d_in[2];
    const float* qkv_w   = (const float*)d_in[3];
    const float* conv_w0 = (const float*)d_in[4];
    const float* conv_b0 = (const float*)d_in[5];
    const float* conv_w1 = (const float*)d_in[6];
    const float* conv_b1 = (const float*)d_in[7];
    const float* proj_w  = (const float*)d_in[8];
    const float* proj_b  = (const float*)d_in[9];
    const float* norm2_w = (const float*)d_in[10];
    const float* norm2_b = (const float*)d_in[11];
    const float* fc1_w   = (const float*)d_in[12];
    const float* fc1_b   = (const float*)d_in[13];
    const float* fc2_w   = (const float*)d_in[14];
    const float* fc2_b   = (const float*)d_in[15];
    float* out = (float*)d_out;

    __nv_bfloat16 *img, *att, *y1, *hbuf, *qkvw, *projw, *fc1w, *fc2w;
    float *xa;
    cudaGetSymbolAddress((void**)&img,   g_img);
    cudaGetSymbolAddress((void**)&att,   g_att);
    cudaGetSymbolAddress((void**)&xa,    g_xa);
    cudaGetSymbolAddress((void**)&y1,    g_y1);
    cudaGetSymbolAddress((void**)&hbuf,  g_h);
    cudaGetSymbolAddress((void**)&qkvw,  g_qkvw);
    cudaGetSymbolAddress((void**)&projw, g_projw);
    cudaGetSymbolAddress((void**)&fc1w,  g_fc1w);
    cudaGetSymbolAddress((void**)&fc2w,  g_fc2w);

    // 0. weight conversion
    cvt4_kernel<<<(HID * CC + 255) / 256, 256>>>(
        qkv_w, qkvw, 3 * CC * CC,
        proj_w, projw, CC * CC,
        fc1_w, fc1w, HID * CC,
        fc2_w, fc2w, CC * HID);

    // 1. LN1 -> bf16
    ln_kernel<<<NTOK / 8, 256>>>(x, norm1_w, norm1_b, img);

    // 2. QKV GEMM, epilogue scatters window-major bf16 q/k/v
    gemm_mma<2><<<dim3(NTOK / GBM, (3 * CC) / GBN), 256>>>(
        img, qkvw, nullptr, nullptr, nullptr, nullptr, NTOK, CC, 3 * CC);

    // 3. Attention + fused LePE: one block per (window, head)
    attn_mma_all<<<dim3(NH, 2 * NWIN), 256>>>(att, conv_w0, conv_b0, conv_w1, conv_b1);

    // 4. proj + bias + residual(x) -> xa
    gemm_mma<0><<<dim3(NTOK / GBM, CC / GBN), 256>>>(
        att, projw, proj_b, x, xa, nullptr, NTOK, CC, CC);

    // 5. LN2 -> bf16
    ln_kernel<<<NTOK / 8, 256>>>(xa, norm2_w, norm2_b, y1);

    // 6. FC1 + bias + GELU -> bf16
    gemm_mma<1><<<dim3(NTOK / GBM, HID / GBN), 256>>>(
        y1, fc1w, fc1_b, nullptr, nullptr, hbuf, NTOK, CC, HID);

    // 7. FC2 + bias + residual(xa) -> out
    gemm_mma<0><<<dim3(NTOK / GBM, CC / GBN), 256>>>(
        hbuf, fc2w, fc2_b, xa, out, nullptr, NTOK, HID, CC);
}

// round 17
// speedup vs baseline: 1.4787x; 1.0774x over previous
#include <cuda_runtime.h>
#include <cuda_bf16.h>
#include <math.h>

// ---------------------------------------------------------------------------
// Problem constants
// ---------------------------------------------------------------------------
#define BB    4
#define TT    8
#define RES   32
#define CC    128
#define LL    (TT * RES * RES)        // 8192
#define NTOK  (BB * LL)               // 32768
#define HID   (4 * CC)                // 512
#define TSP   4
#define WIN   512
#define NWIN  64
#define NH    4
#define HD    16
#define HCH   64

#define QSCALE 0.36067376022224085f   // 0.25 * log2(e)

// ---------------------------------------------------------------------------
// Scratch
// ---------------------------------------------------------------------------
__device__ __nv_bfloat16 g_img[(size_t)NTOK * CC];
__device__ __nv_bfloat16 g_att[(size_t)NTOK * CC];
__device__ float         g_xa [(size_t)NTOK * CC];
__device__ __nv_bfloat16 g_y1 [(size_t)NTOK * CC];
__device__ __nv_bfloat16 g_h  [(size_t)NTOK * HID];
__device__ __nv_bfloat16 g_qkvw[(size_t)3 * CC * CC];
__device__ __nv_bfloat16 g_projw[(size_t)CC * CC];
__device__ __nv_bfloat16 g_fc1w[(size_t)HID * CC];
__device__ __nv_bfloat16 g_fc2w[(size_t)CC * HID];
// window-major attention operands: [branch][win][head][j][d] (q scaled)
__device__ __nv_bfloat16 g_qw[(size_t)2 * NWIN * NH * WIN * HD];
__device__ __nv_bfloat16 g_kw[(size_t)2 * NWIN * NH * WIN * HD];
// transposed V: [branch][win][head][d][j]
__device__ __nv_bfloat16 g_vt[(size_t)2 * NWIN * NH * HD * WIN];

// ---------------------------------------------------------------------------
// fp32 -> bf16 weight conversion
// ---------------------------------------------------------------------------
__global__ void cvt4_kernel(const float* __restrict__ s0, __nv_bfloat16* __restrict__ d0, int n0,
                            const float* __restrict__ s1, __nv_bfloat16* __restrict__ d1, int n1,
                            const float* __restrict__ s2, __nv_bfloat16* __restrict__ d2, int n2,
                            const float* __restrict__ s3, __nv_bfloat16* __restrict__ d3, int n3) {
    int i = blockIdx.x * blockDim.x + threadIdx.x;
    if (i < n0) d0[i] = __float2bfloat16(s0[i]);
    if (i < n1) d1[i] = __float2bfloat16(s1[i]);
    if (i < n2) d2[i] = __float2bfloat16(s2[i]);
    if (i < n3) d3[i] = __float2bfloat16(s3[i]);
}

// ---------------------------------------------------------------------------
// LayerNorm: one warp per token; writes bf16
// ---------------------------------------------------------------------------
__global__ void ln_kernel(const float* __restrict__ x, const float* __restrict__ w,
                          const float* __restrict__ b, __nv_bfloat16* __restrict__ out) {
    int gw   = (blockIdx.x * blockDim.x + threadIdx.x) >> 5;
    int lane = threadIdx.x & 31;
    if (gw >= NTOK) return;
    float4 v = ((const float4*)(x + (size_t)gw * CC))[lane];
    float s = v.x + v.y + v.z + v.w;
    #pragma unroll
    for (int o = 16; o; o >>= 1) s += __shfl_xor_sync(0xffffffffu, s, o);
    float mu = s * (1.0f / CC);
    float dx = v.x - mu, dy = v.y - mu, dz = v.z - mu, dw = v.w - mu;
    float s2 = dx * dx + dy * dy + dz * dz + dw * dw;
    #pragma unroll
    for (int o = 16; o; o >>= 1) s2 += __shfl_xor_sync(0xffffffffu, s2, o);
    float rstd = rsqrtf(s2 * (1.0f / CC) + 1e-5f);
    float4 w4 = ((const float4*)w)[lane];
    float4 b4 = ((const float4*)b)[lane];
    float ox = dx * rstd * w4.x + b4.x;
    float oy = dy * rstd * w4.y + b4.y;
    float oz = dz * rstd * w4.z + b4.z;
    float ow = dw * rstd * w4.w + b4.w;
    __nv_bfloat162* op = (__nv_bfloat162*)(out + (size_t)gw * CC);
    op[lane * 2]     = __floats2bfloat162_rn(ox, oy);
    op[lane * 2 + 1] = __floats2bfloat162_rn(oz, ow);
}

// ---------------------------------------------------------------------------
// bf16 MMA GEMM, K staged in 128-wide chunks (K=128: single load, 1 sync pair).
// MODE: 0 = plain/residual, 1 = +gelu, 2 = qkv window-scatter
// ---------------------------------------------------------------------------
#define GBM 128
#define GBN 64
#define KCH 128
#define KPITCH 136   // halves; row stride 68 words -> conflict-free frag loads

template<int MODE>
__global__ void gemm_mma(const __nv_bfloat16* __restrict__ A, const __nv_bfloat16* __restrict__ W,
                         const float* __restrict__ bias, const float* __restrict__ res,
                         float* __restrict__ outF, __nv_bfloat16* __restrict__ outH,
                         int N, int K, int M) {
    __shared__ __nv_bfloat16 sA[GBM][KPITCH];
    __shared__ __nv_bfloat16 sW[GBN][KPITCH];
    int tid = threadIdx.x;
    int wid = tid >> 5, lane = tid & 31;
    int warp_m = wid >> 1, warp_n = wid & 1;
    int tok0 = blockIdx.x * GBM;
    int f0   = blockIdx.y * GBN;

    float acc[2][4][4];
    #pragma unroll
    for (int i = 0; i < 2; i++)
        #pragma unroll
        for (int j = 0; j < 4; j++)
            #pragma unroll
            for (int r = 0; r < 4; r++) acc[i][j][r] = 0.0f;

    int nk = K / KCH;
    #pragma unroll 1
    for (int it = 0; it < nk; it++) {
        int k0 = it * KCH;
        // stage A: 128 rows x 128 halves = 2048 uint4 (8 per thread)
        #pragma unroll
        for (int p = 0; p < 8; p++) {
            int e = tid + p * 256;
            int row = e >> 4, seg = (e & 15) * 8;
            uint4 v = *(const uint4*)(A + (size_t)(tok0 + row) * K + k0 + seg);
            *(uint4*)(&sA[row][seg]) = v;
        }
        // stage W: 64 rows x 128 halves = 1024 uint4 (4 per thread)
        #pragma unroll
        for (int p = 0; p < 4; p++) {
            int e = tid + p * 256;
            int row = e >> 4, seg = (e & 15) * 8;
            uint4 v = *(const uint4*)(W + (size_t)(f0 + row) * K + k0 + seg);
            *(uint4*)(&sW[row][seg]) = v;
        }
        __syncthreads();
        #pragma unroll
        for (int kk = 0; kk < KCH; kk += 16) {
            unsigned afrag[2][4], bfrag[4][2];
            int rr = (lane >> 2);
            int cc2 = kk + (lane & 3) * 2;
            #pragma unroll
            for (int i = 0; i < 2; i++) {
                int r = warp_m * 32 + i * 16 + rr;
                afrag[i][0] = *(const unsigned*)(&sA[r][cc2]);
                afrag[i][1] = *(const unsigned*)(&sA[r + 8][cc2]);
                afrag[i][2] = *(const unsigned*)(&sA[r][cc2 + 8]);
                afrag[i][3] = *(const unsigned*)(&sA[r + 8][cc2 + 8]);
            }
            #pragma unroll
            for (int j = 0; j < 4; j++) {
                int n = warp_n * 32 + j * 8 + rr;
                bfrag[j][0] = *(const unsigned*)(&sW[n][cc2]);
                bfrag[j][1] = *(const unsigned*)(&sW[n][cc2 + 8]);
            }
            #pragma unroll
            for (int i = 0; i < 2; i++)
                #pragma unroll
                for (int j = 0; j < 4; j++)
                    asm volatile(
                        "mma.sync.aligned.m16n8k16.row.col.f32.bf16.bf16.f32 "
                        "{%0,%1,%2,%3}, {%4,%5,%6,%7}, {%8,%9}, {%0,%1,%2,%3};"
                        : "+f"(acc[i][j][0]), "+f"(acc[i][j][1]),
                          "+f"(acc[i][j][2]), "+f"(acc[i][j][3])
                        : "r"(afrag[i][0]), "r"(afrag[i][1]),
                          "r"(afrag[i][2]), "r"(afrag[i][3]),
                          "r"(bfrag[j][0]), "r"(bfrag[j][1]));
        }
        if (it + 1 < nk) __syncthreads();
    }

    if (MODE == 2) {
        // decode 4 distinct rows (token -> both-branch window coords)
        int bw0[2][2], bw1[2][2], j0[2][2], j1[2][2];
        #pragma unroll
        for (int i = 0; i < 2; i++)
            #pragma unroll
            for (int h = 0; h < 2; h++) {
                int n = tok0 + warp_m * 32 + i * 16 + (lane >> 2) + h * 8;
                int bq = n >> 13, l = n & 8191;
                int tc = l >> 10, hh = (l >> 5) & 31, ww = l & 31;
                int bq2 = bq * 2 + (tc >> 2), ts = tc & 3;
                bw0[i][h] = bq2 * 8 + (ww >> 2);
                j0[i][h]  = ts * 128 + hh * 4 + (ww & 3);
                bw1[i][h] = bq2 * 8 + (hh >> 2);
                j1[i][h]  = ts * 128 + (hh & 3) * 32 + ww;
            }
        #pragma unroll
        for (int j = 0; j < 4; j++) {
            int m = f0 + warp_n * 32 + j * 8 + (lane & 3) * 2;
            int part = m >> 7, mm = m & 127;
            int br = (mm >> 6) & 1, head = (mm >> 4) & 3, d = mm & 15;
            int hb = (br * NWIN * NH) + head;
            #pragma unroll
            for (int i = 0; i < 2; i++)
                #pragma unroll
                for (int h = 0; h < 2; h++) {
                    int bw = br ? bw1[i][h] : bw0[i][h];
                    int jj = br ? j1[i][h] : j0[i][h];
                    size_t base = ((size_t)(hb + bw * NH)) << 13;
                    float v0 = acc[i][j][h * 2 + 0];
                    float v1 = acc[i][j][h * 2 + 1];
                    if (part == 0) {
                        *(__nv_bfloat162*)(g_qw + base + jj * HD + d) =
                            __floats2bfloat162_rn(v0 * QSCALE, v1 * QSCALE);
                    } else if (part == 1) {
                        *(__nv_bfloat162*)(g_kw + base + jj * HD + d) =
                            __floats2bfloat162_rn(v0, v1);
                    } else {
                        g_vt[base + (size_t)d * WIN + jj]       = __float2bfloat16(v0);
                        g_vt[base + (size_t)(d + 1) * WIN + jj] = __float2bfloat16(v1);
                    }
                }
        }
        return;
    }

    #pragma unroll
    for (int i = 0; i < 2; i++) {
        #pragma unroll
        for (int j = 0; j < 4; j++) {
            int rbase = tok0 + warp_m * 32 + i * 16 + (lane >> 2);
            int cbase = f0 + warp_n * 32 + j * 8 + (lane & 3) * 2;
            #pragma unroll
            for (int h = 0; h < 2; h++) {
                int n = rbase + h * 8;
                float v0 = acc[i][j][h * 2 + 0];
                float v1 = acc[i][j][h * 2 + 1];
                if (bias) { v0 += bias[cbase]; v1 += bias[cbase + 1]; }
                if (MODE == 1) {
                    v0 = 0.5f * v0 * (1.0f + erff(v0 * 0.70710678118654752f));
                    v1 = 0.5f * v1 * (1.0f + erff(v1 * 0.70710678118654752f));
                }
                if (res) {
                    float2 rv = *(const float2*)(res + (size_t)n * M + cbase);
                    v0 += rv.x; v1 += rv.y;
                }
                if (outF) {
                    float2 o; o.x = v0; o.y = v1;
                    *(float2*)(outF + (size_t)n * M + cbase) = o;
                }
                if (outH) {
                    *(__nv_bfloat162*)(outH + (size_t)n * M + cbase) =
                        __floats2bfloat162_rn(v0, v1);
                }
            }
        }
    }
}

// ---------------------------------------------------------------------------
// Tensor-core flash attention with fused LePE (R11 version — best measured).
// Grid: (4 q-blocks, NH heads, 2*NWIN windows). 256 threads / 8 warps.
// ---------------------------------------------------------------------------
#define KPIT 24
#define VPIT 520

__device__ __forceinline__ unsigned packbf(float a, float b) {
    __nv_bfloat162 t = __floats2bfloat162_rn(a, b);
    return *(unsigned*)&t;
}
__device__ __forceinline__ float ex2(float x) {
    float y; asm("ex2.approx.ftz.f32 %0, %1;" : "=f"(y) : "f"(x)); return y;
}

template<int Hsp, int Wsp, int nHb, int nWb, int brOff>
__device__ __forceinline__ void attn_body(
        __nv_bfloat16 (*sK)[KPIT], __nv_bfloat16 (*sVT)[VPIT],
        float (*sCW)[27], float* sCB,
        const float* __restrict__ cw, const float* __restrict__ cb,
        __nv_bfloat16* __restrict__ att, int bw) {
    constexpr int HW = Hsp * Wsp;   // 128
    constexpr int BR = (brOff == 0) ? 0 : 1;

    int tid = threadIdx.x, lane = tid & 31, wid = tid >> 5;
    int head = blockIdx.y;

    int wb = bw % nWb;
    int t1 = bw / nWb;
    int hb = t1 % nHb; t1 /= nHb;
    int tb = t1 & 1;
    int bq = t1 >> 1;
    int baseTok = bq * LL + tb * TSP * (RES * RES) + hb * Hsp * RES + wb * Wsp;
    int cbase = brOff + head * HD;

    for (int e = tid; e < HD * 27; e += 256) {
        int d = e / 27, k = e - d * 27;
        sCW[d][k] = cw[(head * HD + d) * 27 + k];
    }
    if (tid < HD) sCB[tid] = cb[head * HD + tid];

    size_t hbase = ((size_t)((BR * NWIN + bw) * NH + head)) << 13;

    // stage K and V^T: pure vector copies
    const uint4* kp = (const uint4*)(g_kw + hbase);
    #pragma unroll
    for (int p = 0; p < 4; p++) {
        int e = tid + p * 256;
        uint4 v = kp[e];
        int j = e >> 1, seg = (e & 1) * 8;
        *(uint4*)(&sK[j][seg]) = v;
    }
    const uint4* vp = (const uint4*)(g_vt + hbase);
    #pragma unroll
    for (int p = 0; p < 4; p++) {
        int e = tid + p * 256;
        uint4 v = vp[e];
        int d = e >> 6, j8 = (e & 63) * 8;
        *(uint4*)(&sVT[d][j8]) = v;
    }

    // Q fragment (pre-scaled bf16, window-major)
    int qr = lane >> 2, kc = (lane & 3) * 2;
    int qbase = blockIdx.x * 128 + wid * 16;
    unsigned qa[4];
    #pragma unroll
    for (int h = 0; h < 2; h++) {
        int j = qbase + qr + h * 8;
        const __nv_bfloat16* qp = g_qw + hbase + j * HD;
        qa[h]     = *(const unsigned*)(qp + kc);
        qa[2 + h] = *(const unsigned*)(qp + kc + 8);
    }
    __syncthreads();

    float O[2][4];
    #pragma unroll
    for (int v = 0; v < 2; v++)
        #pragma unroll
        for (int r = 0; r < 4; r++) O[v][r] = 0.0f;
    float m0 = -1e30f, m1 = -1e30f, l0 = 0.0f, l1 = 0.0f;

    #pragma unroll 1
    for (int ch = 0; ch < 8; ch++) {
        int n0 = ch * 64;
        float S[8][4];
        #pragma unroll
        for (int t = 0; t < 8; t++) {
            S[t][0] = S[t][1] = S[t][2] = S[t][3] = 0.0f;
            unsigned b0 = *(const unsigned*)(&sK[n0 + t * 8 + qr][kc]);
            unsigned b1 = *(const unsigned*)(&sK[n0 + t * 8 + qr][kc + 8]);
            asm volatile(
                "mma.sync.aligned.m16n8k16.row.col.f32.bf16.bf16.f32 "
                "{%0,%1,%2,%3}, {%4,%5,%6,%7}, {%8,%9}, {%0,%1,%2,%3};"
                : "+f"(S[t][0]), "+f"(S[t][1]), "+f"(S[t][2]), "+f"(S[t][3])
                : "r"(qa[0]), "r"(qa[1]), "r"(qa[2]), "r"(qa[3]),
                  "r"(b0), "r"(b1));
        }
        float mx0 = -1e30f, mx1 = -1e30f;
        #pragma unroll
        for (int t = 0; t < 8; t++) {
            mx0 = fmaxf(mx0, fmaxf(S[t][0], S[t][1]));
            mx1 = fmaxf(mx1, fmaxf(S[t][2], S[t][3]));
        }
        mx0 = fmaxf(mx0, __shfl_xor_sync(0xffffffffu, mx0, 1));
        mx0 = fmaxf(mx0, __shfl_xor_sync(0xffffffffu, mx0, 2));
        mx1 = fmaxf(mx1, __shfl_xor_sync(0xffffffffu, mx1, 1));
        mx1 = fmaxf(mx1, __shfl_xor_sync(0xffffffffu, mx1, 2));
        float nm0 = fmaxf(m0, mx0), nm1 = fmaxf(m1, mx1);
        float c0 = ex2(m0 - nm0), c1 = ex2(m1 - nm1);
        m0 = nm0; m1 = nm1;
        l0 *= c0; l1 *= c1;
        #pragma unroll
        for (int v = 0; v < 2; v++) {
            O[v][0] *= c0; O[v][1] *= c0; O[v][2] *= c1; O[v][3] *= c1;
        }
        #pragma unroll
        for (int t = 0; t < 8; t++) {
            S[t][0] = ex2(S[t][0] - m0);
            S[t][1] = ex2(S[t][1] - m0);
            S[t][2] = ex2(S[t][2] - m1);
            S[t][3] = ex2(S[t][3] - m1);
            l0 += S[t][0] + S[t][1];
            l1 += S[t][2] + S[t][3];
        }
        #pragma unroll
        for (int kk = 0; kk < 4; kk++) {
            unsigned a0 = packbf(S[2 * kk][0], S[2 * kk][1]);
            unsigned a1 = packbf(S[2 * kk][2], S[2 * kk][3]);
            unsigned a2 = packbf(S[2 * kk + 1][0], S[2 * kk + 1][1]);
            unsigned a3 = packbf(S[2 * kk + 1][2], S[2 * kk + 1][3]);
            int keyc = n0 + kk * 16 + kc;
            #pragma unroll
            for (int v = 0; v < 2; v++) {
                unsigned b0 = *(const unsigned*)(&sVT[v * 8 + qr][keyc]);
                unsigned b1 = *(const unsigned*)(&sVT[v * 8 + qr][keyc + 8]);
                asm volatile(
                    "mma.sync.aligned.m16n8k16.row.col.f32.bf16.bf16.f32 "
                    "{%0,%1,%2,%3}, {%4,%5,%6,%7}, {%8,%9}, {%0,%1,%2,%3};"
                    : "+f"(O[v][0]), "+f"(O[v][1]), "+f"(O[v][2]), "+f"(O[v][3])
                    : "r"(a0), "r"(a1), "r"(a2), "r"(a3),
                      "r"(b0), "r"(b1));
            }
        }
    }

    l0 += __shfl_xor_sync(0xffffffffu, l0, 1);
    l0 += __shfl_xor_sync(0xffffffffu, l0, 2);
    l1 += __shfl_xor_sync(0xffffffffu, l1, 1);
    l1 += __shfl_xor_sync(0xffffffffu, l1, 2);
    float inv0 = 1.0f / l0, inv1 = 1.0f / l1;

    // epilogue: O/l + fused LePE conv, store bf16 (token-major for proj GEMM)
    #pragma unroll
    for (int h = 0; h < 2; h++) {
        int j = qbase + qr + h * 8;
        int ts = j / HW;
        int rem = j - ts * HW;
        int hs = rem / Wsp;
        int ws = rem - hs * Wsp;
        int n = baseTok + ts * (RES * RES) + hs * RES + ws;
        float inv = h ? inv1 : inv0;

        int d0 = kc, d1 = kc + 1, d2 = 8 + kc, d3 = 9 + kc;
        float acc0 = sCB[d0], acc1 = sCB[d1], acc2 = sCB[d2], acc3 = sCB[d3];
        #pragma unroll
        for (int kt = 0; kt < 3; kt++) {
            int ttc = ts + kt - 1;
            if ((unsigned)ttc >= (unsigned)TSP) continue;
            #pragma unroll
            for (int kh = 0; kh < 3; kh++) {
                int hh = hs + kh - 1;
                if ((unsigned)hh >= (unsigned)Hsp) continue;
                #pragma unroll
                for (int kw2 = 0; kw2 < 3; kw2++) {
                    int ww = ws + kw2 - 1;
                    if ((unsigned)ww >= (unsigned)Wsp) continue;
                    int jp = ttc * HW + hh * Wsp + ww;
                    int widx = kt * 9 + kh * 3 + kw2;
                    acc0 += sCW[d0][widx] * __bfloat162float(sVT[d0][jp]);
                    acc1 += sCW[d1][widx] * __bfloat162float(sVT[d1][jp]);
                    acc2 += sCW[d2][widx] * __bfloat162float(sVT[d2][jp]);
                    acc3 += sCW[d3][widx] * __bfloat162float(sVT[d3][jp]);
                }
            }
        }
        float o0 = O[0][h * 2 + 0] * inv + acc0;
        float o1 = O[0][h * 2 + 1] * inv + acc1;
        float o2 = O[1][h * 2 + 0] * inv + acc2;
        float o3 = O[1][h * 2 + 1] * inv + acc3;
        __nv_bfloat16* ap = att + (size_t)n * CC + cbase;
        *(__nv_bfloat162*)(ap + kc)     = __floats2bfloat162_rn(o0, o1);
        *(__nv_bfloat162*)(ap + 8 + kc) = __floats2bfloat162_rn(o2, o3);
    }
}

__global__ __launch_bounds__(256, 2) void attn_mma_all(
        __nv_bfloat16* __restrict__ att,
        const float* __restrict__ cw0, const float* __restrict__ cb0,
        const float* __restrict__ cw1, const float* __restrict__ cb1) {
    __shared__ __nv_bfloat16 sK[WIN][KPIT];
    __shared__ __nv_bfloat16 sVT[HD][VPIT];
    __shared__ float sCW[HD][27];
    __shared__ float sCB[HD];

    int bz = blockIdx.z;
    if (bz < NWIN) {
        attn_body<RES, TSP, 1, 8, 0>(sK, sVT, sCW, sCB, cw0, cb0, att, bz);
    } else {
        attn_body<TSP, RES, 8, 1, HCH>(sK, sVT, sCW, sCB, cw1, cb1, att, bz - NWIN);
    }
}

// ---------------------------------------------------------------------------
// Launch
// ---------------------------------------------------------------------------
extern "C" void kernel_launch(void* const* d_in, const int* in_sizes, int n_in,
                              void* d_out, int out_size) {
    const float* x       = (const float*)d_in[0];
    const float* norm1_w = (const float*)d_in[1];
    const float* norm1_b = (const float*)d_in[2];
    const float* qkv_w   = (const float*)d_in[3];
    const float* conv_w0 = (const float*)d_in[4];
    const float* conv_b0 = (const float*)d_in[5];
    const float* conv_w1 = (const float*)d_in[6];
    const float* conv_b1 = (const float*)d_in[7];
    const float* proj_w  = (const float*)d_in[8];
    const float* proj_b  = (const float*)d_in[9];
    const float* norm2_w = (const float*)d_in[10];
    const float* norm2_b = (const float*)d_in[11];
    const float* fc1_w   = (const float*)d_in[12];
    const float* fc1_b   = (const float*)d_in[13];
    const float* fc2_w   = (const float*)d_in[14];
    const float* fc2_b   = (const float*)d_in[15];
    float* out = (float*)d_out;

    __nv_bfloat16 *img, *att, *y1, *hbuf, *qkvw, *projw, *fc1w, *fc2w;
    float *xa;
    cudaGetSymbolAddress((void**)&img,   g_img);
    cudaGetSymbolAddress((void**)&att,   g_att);
    cudaGetSymbolAddress((void**)&xa,    g_xa);
    cudaGetSymbolAddress((void**)&y1,    g_y1);
    cudaGetSymbolAddress((void**)&hbuf,  g_h);
    cudaGetSymbolAddress((void**)&qkvw,  g_qkvw);
    cudaGetSymbolAddress((void**)&projw, g_projw);
    cudaGetSymbolAddress((void**)&fc1w,  g_fc1w);
    cudaGetSymbolAddress((void**)&fc2w,  g_fc2w);

    // 0. weight conversion
    cvt4_kernel<<<(HID * CC + 255) / 256, 256>>>(
        qkv_w, qkvw, 3 * CC * CC,
        proj_w, projw, CC * CC,
        fc1_w, fc1w, HID * CC,
        fc2_w, fc2w, CC * HID);

    // 1. LN1 -> bf16
    ln_kernel<<<NTOK / 8, 256>>>(x, norm1_w, norm1_b, img);

    // 2. QKV GEMM, epilogue scatters window-major bf16 q/k/v
    gemm_mma<2><<<dim3(NTOK / GBM, (3 * CC) / GBN), 256>>>(
        img, qkvw, nullptr, nullptr, nullptr, nullptr, NTOK, CC, 3 * CC);

    // 3. Attention + fused LePE, both branches in one launch (R11 layout)
    attn_mma_all<<<dim3(4, NH, 2 * NWIN), 256>>>(att, conv_w0, conv_b0, conv_w1, conv_b1);

    // 4. proj + bias + residual(x) -> xa
    gemm_mma<0><<<dim3(NTOK / GBM, CC / GBN), 256>>>(
        att, projw, proj_b, x, xa, nullptr, NTOK, CC, CC);

    // 5. LN2 -> bf16
    ln_kernel<<<NTOK / 8, 256>>>(xa, norm2_w, norm2_b, y1);

    // 6. FC1 + bias + GELU -> bf16
    gemm_mma<1><<<dim3(NTOK / GBM, HID / GBN), 256>>>(
        y1, fc1w, fc1_b, nullptr, nullptr, hbuf, NTOK, CC, HID);

    // 7. FC2 + bias + residual(xa) -> out
    gemm_mma<0><<<dim3(NTOK / GBM, CC / GBN), 256>>>(
        hbuf, fc2w, fc2_b, xa, out, nullptr, NTOK, HID, CC);
}